// round 15
// baseline (speedup 1.0000x reference)
#include <cuda_runtime.h>
#include <stdint.h>

#define NUM_CLASSES 32000
#define HALF_F 16000                 // floats per CTA (half row)
#define H8 2000                      // 32-byte chunks per half
#define ALPHA 0.95f
#define THREADS 512
#define NWARP (THREADS / 32)         // 16
#define P1ITER 4                     // ceil(2000/512), last iter: tid < 464
#define P2ITER 4                     // same chunking for 256-bit phase 2

// 256-bit load with L2::evict_last (sm_103a needs v8.b32 for L2 hints).
// Pins the line in L2 until the phase-2 re-read. Not volatile: pure loads,
// compiler may hoist/batch for MLP.
__device__ __forceinline__ float ldg_el_sum32(const void* p) {
    unsigned u0, u1, u2, u3, u4, u5, u6, u7;
    asm("ld.global.L2::evict_last.v8.b32 {%0,%1,%2,%3,%4,%5,%6,%7}, [%8];"
        : "=r"(u0), "=r"(u1), "=r"(u2), "=r"(u3),
          "=r"(u4), "=r"(u5), "=r"(u6), "=r"(u7)
        : "l"(p));
    const float a = __uint_as_float(u0), b = __uint_as_float(u1);
    const float c = __uint_as_float(u2), d = __uint_as_float(u3);
    const float e = __uint_as_float(u4), f = __uint_as_float(u5);
    const float g = __uint_as_float(u6), h = __uint_as_float(u7);
    return ((a + b) + (c + d)) + ((e + f) + (g + h));
}

// 256-bit re-read with L2::evict_first: demotes the pinned line at its last
// use (frees evict_last capacity for later rows), half the load issues of
// 2x LDG.128.
struct F8 { float4 a, b; };
__device__ __forceinline__ F8 ldg_ef_32(const void* p) {
    unsigned u0, u1, u2, u3, u4, u5, u6, u7;
    asm("ld.global.L2::evict_first.v8.b32 {%0,%1,%2,%3,%4,%5,%6,%7}, [%8];"
        : "=r"(u0), "=r"(u1), "=r"(u2), "=r"(u3),
          "=r"(u4), "=r"(u5), "=r"(u6), "=r"(u7)
        : "l"(p));
    F8 r;
    r.a.x = __uint_as_float(u0); r.a.y = __uint_as_float(u1);
    r.a.z = __uint_as_float(u2); r.a.w = __uint_as_float(u3);
    r.b.x = __uint_as_float(u4); r.b.y = __uint_as_float(u5);
    r.b.z = __uint_as_float(u6); r.b.w = __uint_as_float(u7);
    return r;
}

__device__ __forceinline__ uint32_t smem_addr_u32(const void* p) {
    uint32_t a;
    asm("{ .reg .u64 t; cvta.to.shared.u64 t, %1; cvt.u32.u64 %0, t; }"
        : "=r"(a) : "l"(p));
    return a;
}

// 2-CTA cluster per row: each CTA owns a 64 KB half-row.
//   - pinned set = 592 CTAs x 64 KB ~ 38 MB < ~45 MB effective evict_last
//     capacity -> floor DRAM traffic (proven R14: 1.005 GB)
//   - 32 regs, 4 CTAs/SM -> 86% occupancy (proven R14)
//   - 256-bit loads both phases -> halved load-issue count (new in R15)
//   - cross-CTA sum exchange: st.shared::cluster + one cluster barrier
//   - phase 2 reversed (hottest L2 lines re-read first)
__global__ __launch_bounds__(THREADS, 4) __cluster_dims__(2, 1, 1)
void distill_kernel(const float* __restrict__ x,
                    const void*  __restrict__ labels,
                    float*       __restrict__ out) {
    __shared__ float warp_sums[NWARP];
    __shared__ float peer_sum;               // written by the PEER CTA

    const int half = blockIdx.x & 1;         // cluster cta rank
    const int row  = blockIdx.x >> 1;
    const int tid  = threadIdx.x;

    const float* __restrict__ xrow = x + (size_t)row * NUM_CLASSES;
    const float* __restrict__ xh   = xrow + half * HALF_F;
    float* __restrict__ oh = out + (size_t)row * NUM_CLASSES + half * HALF_F;

    // Inline label-dtype detection: probe 4 u64 words (in-bounds for both
    // int64[4096] and int32[4096] layouts). True int64 labels are all
    // < 32000; an int32 buffer viewed as u64 is < 32000 only when the
    // odd-position label is exactly 0 — P(4 in a row) ~ (1/32000)^4 ~ 1e-18.
    const unsigned long long* lu = (const unsigned long long*)labels;
    const bool is64 = (lu[0] < (unsigned long long)NUM_CLASSES) &
                      (lu[1] < (unsigned long long)NUM_CLASSES) &
                      (lu[2] < (unsigned long long)NUM_CLASSES) &
                      (lu[3] < (unsigned long long)NUM_CLASSES);

    int lab;
    if (is64) lab = (int)(((const long long*)labels)[row]);
    else      lab = ((const int*)labels)[row];
    const float t = __ldg(xrow + lab);       // both CTAs load t (4B, L2-hot)

    // ---- Phase 1: half-row sum, 32-B loads pinned evict_last in L2 ----
    float sum = 0.0f;
    #pragma unroll
    for (int k = 0; k < P1ITER; k++) {
        const int j = tid + k * THREADS;
        if (k < P1ITER - 1 || j < H8) {
            sum += ldg_el_sum32(reinterpret_cast<const char*>(xh) + (size_t)j * 32);
        }
    }

    // ---- Block reduce (single barrier) ----
    #pragma unroll
    for (int off = 16; off > 0; off >>= 1)
        sum += __shfl_down_sync(0xffffffffu, sum, off);
    if ((tid & 31) == 0) warp_sums[tid >> 5] = sum;
    __syncthreads();
    float S_local = 0.0f;
    #pragma unroll
    for (int w = 0; w < NWARP; w++) S_local += warp_sums[w];

    // ---- Cross-CTA exchange: push my half-sum into the peer's smem ----
    if (tid == 0) {
        const uint32_t laddr = smem_addr_u32(&peer_sum);
        const uint32_t prank = half ^ 1;
        asm volatile(
            "{ .reg .b32 r;\n\t"
            "mapa.shared::cluster.u32 r, %0, %1;\n\t"
            "st.shared::cluster.f32 [r], %2; }"
            :: "r"(laddr), "r"(prank), "f"(S_local) : "memory");
    }
    asm volatile("barrier.cluster.arrive.aligned;" ::: "memory");
    asm volatile("barrier.cluster.wait.aligned;"   ::: "memory");

    const float S = S_local + peer_sum;
    const float s = ALPHA / (1.0f + S - 2.0f * t);
    const float corr = 1.0f - s * S;

    // Label ownership within this half: chunk j holds local float4 indices
    // 2j and 2j+1; compare against the label's local float4 index.
    const int li   = lab - half * HALF_F;    // may be out of [0,HALF_F)
    const int lab4 = li >> 2;
    const int labc = li & 3;

    // ---- Phase 2: 256-bit re-read from pinned L2 (evict_first), REVERSED ----
    float4* __restrict__ oh4 = reinterpret_cast<float4*>(oh);
    #pragma unroll
    for (int k = P2ITER - 1; k >= 0; k--) {
        const int j = tid + k * THREADS;
        if (k < P2ITER - 1 || j < H8) {
            F8 w = ldg_ef_32(reinterpret_cast<const char*>(xh) + (size_t)j * 32);
            float4 oa, ob;
            oa.x = s * w.a.x;  oa.y = s * w.a.y;
            oa.z = s * w.a.z;  oa.w = s * w.a.w;
            ob.x = s * w.b.x;  ob.y = s * w.b.y;
            ob.z = s * w.b.z;  ob.w = s * w.b.w;
            const int i0 = 2 * j;
            if (i0 == lab4)     reinterpret_cast<float*>(&oa)[labc] += corr;
            if (i0 + 1 == lab4) reinterpret_cast<float*>(&ob)[labc] += corr;
            oh4[i0]     = oa;
            oh4[i0 + 1] = ob;
        }
    }
}

extern "C" void kernel_launch(void* const* d_in, const int* in_sizes, int n_in,
                              void* d_out, int out_size) {
    const float* teacher_logits = (const float*)d_in[0];
    const void*  true_labels    = d_in[1];
    float* out = (float*)d_out;

    const int batch = in_sizes[1];   // 4096 rows

    distill_kernel<<<2 * batch, THREADS>>>(teacher_logits, true_labels, out);
}

// round 16
// speedup vs baseline: 1.0351x; 1.0351x over previous
#include <cuda_runtime.h>
#include <stdint.h>

#define NUM_CLASSES 32000
#define HALF_F 16000                 // floats per CTA (half row)
#define H8 2000                      // 32-byte chunks per half
#define H4 4000                      // float4 slots per half
#define ALPHA 0.95f
#define THREADS 512
#define NWARP (THREADS / 32)         // 16
#define P1ITER 4                     // ceil(2000/512), last iter: tid < 464
#define P2ITER 8                     // ceil(4000/512), last iter: tid < 416

// 256-bit load with L2::evict_last (sm_103a needs v8.b32 for L2 hints).
// Pins the line in L2 until the phase-2 re-read. Not volatile: pure loads,
// compiler may hoist/batch for MLP.
__device__ __forceinline__ float ldg_el_sum32(const void* p) {
    unsigned u0, u1, u2, u3, u4, u5, u6, u7;
    asm("ld.global.L2::evict_last.v8.b32 {%0,%1,%2,%3,%4,%5,%6,%7}, [%8];"
        : "=r"(u0), "=r"(u1), "=r"(u2), "=r"(u3),
          "=r"(u4), "=r"(u5), "=r"(u6), "=r"(u7)
        : "l"(p));
    const float a = __uint_as_float(u0), b = __uint_as_float(u1);
    const float c = __uint_as_float(u2), d = __uint_as_float(u3);
    const float e = __uint_as_float(u4), f = __uint_as_float(u5);
    const float g = __uint_as_float(u6), h = __uint_as_float(u7);
    return ((a + b) + (c + d)) + ((e + f) + (g + h));
}

__device__ __forceinline__ uint32_t smem_addr_u32(const void* p) {
    uint32_t a;
    asm("{ .reg .u64 t; cvta.to.shared.u64 t, %1; cvt.u32.u64 %0, t; }"
        : "=r"(a) : "l"(p));
    return a;
}

// 2-CTA cluster per row: each CTA owns a 64 KB half-row.
//   - pinned set = 592 CTAs x 64 KB ~ 38 MB < ~45 MB effective evict_last
//     capacity -> floor DRAM traffic (proven R14: 1.005 GB)
//   - 32 regs, 4 CTAs/SM -> 86% occupancy (proven R14)
//   - phase 2: 128-bit loads/stores, thread-contiguous (R15 showed 256-bit
//     phase-2 loads force strided stores -> doubled store wavefronts)
//   - NEW: st.async + mbarrier sum exchange (lighter than full cluster
//     barrier at the dependency point); label correction hoisted out of the
//     phase-2 loop (closed-form value, same-thread overwrite)
__global__ __launch_bounds__(THREADS, 4) __cluster_dims__(2, 1, 1)
void distill_kernel(const float* __restrict__ x,
                    const void*  __restrict__ labels,
                    float*       __restrict__ out) {
    __shared__ float warp_sums[NWARP];
    __shared__ float peer_sum;                       // delivered by peer's st.async
    __shared__ __align__(8) unsigned long long mbar;

    const int half = blockIdx.x & 1;                 // cluster cta rank
    const int row  = blockIdx.x >> 1;
    const int tid  = threadIdx.x;

    // Init mbarrier (count=1: our own expect_tx arrival), then split cluster
    // barrier: arrive NOW (guards peer's init visibility), wait after phase 1
    // (fast path — peer arrived ~at kernel start).
    if (tid == 0) {
        asm volatile("mbarrier.init.shared.b64 [%0], 1;"
                     :: "r"(smem_addr_u32(&mbar)) : "memory");
    }
    asm volatile("barrier.cluster.arrive.aligned;" ::: "memory");

    const float* __restrict__ xrow = x + (size_t)row * NUM_CLASSES;
    const float* __restrict__ xh   = xrow + half * HALF_F;
    const float4* __restrict__ xh4 = reinterpret_cast<const float4*>(xh);
    float* __restrict__ oh = out + (size_t)row * NUM_CLASSES + half * HALF_F;
    float4* __restrict__ oh4 = reinterpret_cast<float4*>(oh);

    // Inline label-dtype detection: probe 4 u64 words (in-bounds for both
    // int64[4096] and int32[4096] layouts). True int64 labels are all
    // < 32000; an int32 buffer viewed as u64 is < 32000 only when the
    // odd-position label is exactly 0 — P(4 in a row) ~ (1/32000)^4 ~ 1e-18.
    const unsigned long long* lu = (const unsigned long long*)labels;
    const bool is64 = (lu[0] < (unsigned long long)NUM_CLASSES) &
                      (lu[1] < (unsigned long long)NUM_CLASSES) &
                      (lu[2] < (unsigned long long)NUM_CLASSES) &
                      (lu[3] < (unsigned long long)NUM_CLASSES);

    int lab;
    if (is64) lab = (int)(((const long long*)labels)[row]);
    else      lab = ((const int*)labels)[row];
    const float t = __ldg(xrow + lab);               // both CTAs load t (4B, L2-hot)

    // ---- Phase 1: half-row sum, 32-B loads pinned evict_last in L2 ----
    float sum = 0.0f;
    #pragma unroll
    for (int k = 0; k < P1ITER; k++) {
        const int j = tid + k * THREADS;
        if (k < P1ITER - 1 || j < H8) {
            sum += ldg_el_sum32(reinterpret_cast<const char*>(xh) + (size_t)j * 32);
        }
    }

    // ---- Block reduce (single barrier); every thread ends with S_local ----
    #pragma unroll
    for (int off = 16; off > 0; off >>= 1)
        sum += __shfl_down_sync(0xffffffffu, sum, off);
    if ((tid & 31) == 0) warp_sums[tid >> 5] = sum;
    __syncthreads();
    float S_local = 0.0f;
    #pragma unroll
    for (int w = 0; w < NWARP; w++) S_local += warp_sums[w];

    // ---- Cross-CTA exchange: st.async half-sum into peer smem + mbarrier ----
    asm volatile("barrier.cluster.wait.aligned;" ::: "memory");  // peer init done
    if (tid == 0) {
        const uint32_t l_ps = smem_addr_u32(&peer_sum);
        const uint32_t l_mb = smem_addr_u32(&mbar);
        const uint32_t prank = half ^ 1;
        asm volatile(
            "{ .reg .b32 rps, rmb;\n\t"
            "mapa.shared::cluster.u32 rps, %0, %2;\n\t"
            "mapa.shared::cluster.u32 rmb, %1, %2;\n\t"
            "st.async.shared::cluster.mbarrier::complete_tx::bytes.b32 [rps], %3, [rmb]; }"
            :: "r"(l_ps), "r"(l_mb), "r"(prank), "r"(__float_as_uint(S_local))
            : "memory");
        // Our arrival (count=1) + expect 4 tx bytes from the peer.
        asm volatile("mbarrier.arrive.expect_tx.shared.b64 _, [%0], 4;"
                     :: "r"(l_mb) : "memory");
        asm volatile(
            "{ .reg .pred p;\n\t"
            "WL_%=:\n\t"
            "mbarrier.try_wait.parity.acquire.cta.shared::cta.b64 p, [%0], 0;\n\t"
            "@p bra WD_%=;\n\t"
            "bra WL_%=;\n\t"
            "WD_%=: }"
            :: "r"(l_mb) : "memory");
    }
    __syncthreads();                                 // publish peer_sum to all

    const float S = S_local + peer_sum;
    const float s = ALPHA / (1.0f + S - 2.0f * t);
    const float corr = 1.0f - s * S;

    // ---- Phase 2: re-read from pinned L2 (evict-first), REVERSED; no
    //      in-loop label check ----
    #pragma unroll
    for (int k = P2ITER - 1; k >= 0; k--) {
        const int i = tid + k * THREADS;
        if (k < P2ITER - 1 || i < H4) {
            const float4 w = __ldcs(&xh4[i]);
            float4 o;
            o.x = s * w.x;
            o.y = s * w.y;
            o.z = s * w.z;
            o.w = s * w.w;
            oh4[i] = o;
        }
    }

    // ---- Label correction: closed-form overwrite by the slot's owning
    //      thread (same thread wrote oh4[lab4] above -> program-order safe).
    const int li = lab - half * HALF_F;              // local float index
    if (li >= 0 && li < HALF_F && ((li >> 2) & (THREADS - 1)) == tid) {
        oh[li] = s * t + corr;
    }
}

extern "C" void kernel_launch(void* const* d_in, const int* in_sizes, int n_in,
                              void* d_out, int out_size) {
    const float* teacher_logits = (const float*)d_in[0];
    const void*  true_labels    = d_in[1];
    float* out = (float*)d_out;

    const int batch = in_sizes[1];   // 4096 rows

    distill_kernel<<<2 * batch, THREADS>>>(teacher_logits, true_labels, out);
}

// round 17
// speedup vs baseline: 1.1337x; 1.0953x over previous
#include <cuda_runtime.h>
#include <stdint.h>

#define NUM_CLASSES 32000
#define HALF_F 16000                 // floats per CTA (half row)
#define H8 2000                      // 32-byte chunks per half
#define H4 4000                      // float4 slots per half
#define ALPHA 0.95f
#define THREADS 512
#define NWARP (THREADS / 32)         // 16
#define P1ITER 4                     // ceil(2000/512), last iter: tid < 464
#define P2ITER 8                     // ceil(4000/512), last iter: tid < 416

// 256-bit load with L2::evict_last (sm_103a needs v8.b32 for L2 hints).
// Pins the line in L2 until the phase-2 re-read. Not volatile: pure loads,
// compiler may hoist/batch for MLP.
__device__ __forceinline__ float ldg_el_sum32(const void* p) {
    unsigned u0, u1, u2, u3, u4, u5, u6, u7;
    asm("ld.global.L2::evict_last.v8.b32 {%0,%1,%2,%3,%4,%5,%6,%7}, [%8];"
        : "=r"(u0), "=r"(u1), "=r"(u2), "=r"(u3),
          "=r"(u4), "=r"(u5), "=r"(u6), "=r"(u7)
        : "l"(p));
    const float a = __uint_as_float(u0), b = __uint_as_float(u1);
    const float c = __uint_as_float(u2), d = __uint_as_float(u3);
    const float e = __uint_as_float(u4), f = __uint_as_float(u5);
    const float g = __uint_as_float(u6), h = __uint_as_float(u7);
    return ((a + b) + (c + d)) + ((e + f) + (g + h));
}

__device__ __forceinline__ uint32_t smem_addr_u32(const void* p) {
    uint32_t a;
    asm("{ .reg .u64 t; cvta.to.shared.u64 t, %1; cvt.u32.u64 %0, t; }"
        : "=r"(a) : "l"(p));
    return a;
}

// 2-CTA cluster per row: each CTA owns a 64 KB half-row. R14 structure
// (best measured: kernel 159.1us, floor traffic, 86% occ) with ONE delta:
// the label correction is hoisted out of the phase-2 loop (closed-form
// value s*t + corr, overwritten by the slot's owning thread afterwards).
//   - pinned set = 592 CTAs x 64 KB ~ 38 MB < ~45 MB effective evict_last
//     capacity -> floor DRAM traffic
//   - 32 regs, 4 CTAs/SM -> ~86% occupancy
//   - cross-CTA sum exchange: mapa + st.shared::cluster + full cluster
//     barrier (R16 proved the st.async/mbarrier variant is SLOWER: the
//     single-thread spin serializes the CTA)
//   - phase 2 reversed (hottest L2 lines re-read first), branch-free body
__global__ __launch_bounds__(THREADS, 4) __cluster_dims__(2, 1, 1)
void distill_kernel(const float* __restrict__ x,
                    const void*  __restrict__ labels,
                    float*       __restrict__ out) {
    __shared__ float warp_sums[NWARP];
    __shared__ float peer_sum;               // written by the PEER CTA

    const int half = blockIdx.x & 1;         // cluster cta rank
    const int row  = blockIdx.x >> 1;
    const int tid  = threadIdx.x;

    const float* __restrict__ xrow = x + (size_t)row * NUM_CLASSES;
    const float* __restrict__ xh   = xrow + half * HALF_F;
    const float4* __restrict__ xh4 = reinterpret_cast<const float4*>(xh);
    float* __restrict__ oh = out + (size_t)row * NUM_CLASSES + half * HALF_F;
    float4* __restrict__ oh4 = reinterpret_cast<float4*>(oh);

    // Inline label-dtype detection: probe 4 u64 words (in-bounds for both
    // int64[4096] and int32[4096] layouts). True int64 labels are all
    // < 32000; an int32 buffer viewed as u64 is < 32000 only when the
    // odd-position label is exactly 0 — P(4 in a row) ~ (1/32000)^4 ~ 1e-18.
    const unsigned long long* lu = (const unsigned long long*)labels;
    const bool is64 = (lu[0] < (unsigned long long)NUM_CLASSES) &
                      (lu[1] < (unsigned long long)NUM_CLASSES) &
                      (lu[2] < (unsigned long long)NUM_CLASSES) &
                      (lu[3] < (unsigned long long)NUM_CLASSES);

    int lab;
    if (is64) lab = (int)(((const long long*)labels)[row]);
    else      lab = ((const int*)labels)[row];
    const float t = __ldg(xrow + lab);       // both CTAs load t (4B, L2-hot)

    // ---- Phase 1: half-row sum, 32-B loads pinned evict_last in L2 ----
    float sum = 0.0f;
    #pragma unroll
    for (int k = 0; k < P1ITER; k++) {
        const int j = tid + k * THREADS;
        if (k < P1ITER - 1 || j < H8) {
            sum += ldg_el_sum32(reinterpret_cast<const char*>(xh) + (size_t)j * 32);
        }
    }

    // ---- Block reduce (single barrier) ----
    #pragma unroll
    for (int off = 16; off > 0; off >>= 1)
        sum += __shfl_down_sync(0xffffffffu, sum, off);
    if ((tid & 31) == 0) warp_sums[tid >> 5] = sum;
    __syncthreads();
    float S_local = 0.0f;
    #pragma unroll
    for (int w = 0; w < NWARP; w++) S_local += warp_sums[w];

    // ---- Cross-CTA exchange: push my half-sum into the peer's smem ----
    if (tid == 0) {
        const uint32_t laddr = smem_addr_u32(&peer_sum);
        const uint32_t prank = half ^ 1;
        asm volatile(
            "{ .reg .b32 r;\n\t"
            "mapa.shared::cluster.u32 r, %0, %1;\n\t"
            "st.shared::cluster.f32 [r], %2; }"
            :: "r"(laddr), "r"(prank), "f"(S_local) : "memory");
    }
    asm volatile("barrier.cluster.arrive.aligned;" ::: "memory");
    asm volatile("barrier.cluster.wait.aligned;"   ::: "memory");

    const float S = S_local + peer_sum;
    const float s = ALPHA / (1.0f + S - 2.0f * t);
    const float corr = 1.0f - s * S;

    // ---- Phase 2: re-read from pinned L2 (evict-first), REVERSED,
    //      branch-free body (no in-loop label check) ----
    #pragma unroll
    for (int k = P2ITER - 1; k >= 0; k--) {
        const int i = tid + k * THREADS;
        if (k < P2ITER - 1 || i < H4) {
            const float4 w = __ldcs(&xh4[i]);
            float4 o;
            o.x = s * w.x;
            o.y = s * w.y;
            o.z = s * w.z;
            o.w = s * w.w;
            oh4[i] = o;
        }
    }

    // ---- Label correction: closed-form overwrite by the slot's owning
    //      thread (same thread wrote oh4[lab4] above -> program-order safe).
    const int li = lab - half * HALF_F;      // local float index in this half
    if (li >= 0 && li < HALF_F && ((li >> 2) & (THREADS - 1)) == tid) {
        oh[li] = s * t + corr;
    }
}

extern "C" void kernel_launch(void* const* d_in, const int* in_sizes, int n_in,
                              void* d_out, int out_size) {
    const float* teacher_logits = (const float*)d_in[0];
    const void*  true_labels    = d_in[1];
    float* out = (float*)d_out;

    const int batch = in_sizes[1];   // 4096 rows

    distill_kernel<<<2 * batch, THREADS>>>(teacher_logits, true_labels, out);
}